// round 15
// baseline (speedup 1.0000x reference)
#include <cuda_runtime.h>
#include <cuda_fp16.h>

typedef unsigned int u32;
typedef unsigned long long u64;

#define BB   16
#define CC   256
#define LL   4096
#define NHH  8
#define HCC  32
#define FH   512
#define FH2  1024
#define NPIX (BB*LL)
#define NSP  2

// ---------------------------------------------------------------------------
// Scratch
// ---------------------------------------------------------------------------
__device__ float g_wsq[CC],  g_wbq[CC];
__device__ float g_wskv[2*CC], g_wbkv[2*CC];
__device__ float g_ws1[FH2], g_wb1v[FH2];
__device__ float g_mu_o[NPIX], g_rs_o[NPIX];
__device__ float g_mu_s[NPIX], g_rs_s[NPIX];
__device__ float g_mu_x[NPIX], g_rs_x[NPIX];
__device__ __align__(128) u32 g_Aq[CC*128];
__device__ __align__(128) u32 g_Akv[2*CC*128];
__device__ __align__(128) u32 g_A1[FH2*128];
__device__ __align__(128) u32 g_Ao[CC*128];
__device__ __align__(128) u32 g_A2[CC*256];
__device__ __align__(128) u32 g_o16[BB*CC*(LL/2)];
__device__ __align__(128) u32 g_s16[BB*CC*(LL/2)];
__device__ __align__(128) u32 g_q16[BB*CC*(LL/2)];
__device__ __align__(128) u32 g_kv16[BB*2*CC*(LL/2)];
__device__ __align__(128) u32 g_x16[BB*CC*(LL/2)];
__device__ __align__(128) u32 g_hg[BB*FH*(LL/2)];
__device__ __align__(128) float g_Sp[BB*NHH*NSP*HCC*HCC];
__device__ __align__(128) u32 g_A16[BB*NHH*HCC*(HCC/2)];

// ---------------------------------------------------------------------------
// PTX helpers
// ---------------------------------------------------------------------------
__device__ __forceinline__ u32 smem_u32(const void* p) {
    u32 a;
    asm("{ .reg .u64 t; cvta.to.shared.u64 t, %1; cvt.u32.u64 %0, t; }" : "=r"(a) : "l"(p));
    return a;
}
#define LDSM_X4(r0,r1,r2,r3,addr) \
    asm volatile("ldmatrix.sync.aligned.m8n8.x4.shared.b16 {%0,%1,%2,%3}, [%4];" \
        : "=r"(r0),"=r"(r1),"=r"(r2),"=r"(r3) : "r"(addr))
#define LDSM_X4_T(r0,r1,r2,r3,addr) \
    asm volatile("ldmatrix.sync.aligned.m8n8.x4.trans.shared.b16 {%0,%1,%2,%3}, [%4];" \
        : "=r"(r0),"=r"(r1),"=r"(r2),"=r"(r3) : "r"(addr))
#define MMA_F16(d, a, b0, b1) \
    asm volatile("mma.sync.aligned.m16n8k16.row.col.f32.f16.f16.f32 " \
        "{%0,%1,%2,%3}, {%4,%5,%6,%7}, {%8,%9}, {%0,%1,%2,%3};" \
        : "+f"((d)[0]),"+f"((d)[1]),"+f"((d)[2]),"+f"((d)[3]) \
        : "r"((a)[0]),"r"((a)[1]),"r"((a)[2]),"r"((a)[3]), "r"(b0),"r"(b1))
#define CP16(dst, src) \
    asm volatile("cp.async.cg.shared.global [%0], [%1], 16;" \
        :: "r"(dst), "l"(src) : "memory")
#define CP_COMMIT() asm volatile("cp.async.commit_group;" ::: "memory")
#define CP_WAIT(n)  asm volatile("cp.async.wait_group %0;" :: "n"(n) : "memory")

__device__ __forceinline__ u32 packf16(float a, float b) {
    __half2 h = __floats2half2_rn(a, b);
    return *(u32*)&h;
}
__device__ __forceinline__ float2 unpackf16(u32 w) {
    __half2 h = *(__half2*)&w;
    return __half22float2(h);
}

// ---------------------------------------------------------------------------
// Prep (all five weight matrices, one launch)
// ---------------------------------------------------------------------------
__global__ void prep_fold(const float* __restrict__ Wq, const float* __restrict__ Wk,
                          const float* __restrict__ Wv, const float* __restrict__ W1,
                          const float* __restrict__ Wo, const float* __restrict__ W2,
                          const float* __restrict__ gopt, const float* __restrict__ bopt,
                          const float* __restrict__ gsar, const float* __restrict__ bsar,
                          const float* __restrict__ gffn, const float* __restrict__ bffn,
                          const float* __restrict__ b1)
{
    int row = blockIdx.x;
    int c   = threadIdx.x;
    if (row >= 1792) {
        float w; u32* dst; int di;
        if (row < 2048) {
            int m = row - 1792;
            w = Wo[m*CC + c];
            dst = g_Ao; di = m*128 + (c>>1);
        } else {
            int r2 = row - 2048;
            int m = r2 >> 1, half = r2 & 1;
            int cg = half*256 + c;
            w = W2[m*512 + cg];
            dst = g_A2; di = m*256 + (cg>>1);
        }
        u32 hu = (u32)__half_as_ushort(__float2half_rn(w));
        u32 hp = __shfl_xor_sync(0xffffffffu, hu, 1);
        if (!(c & 1)) dst[di] = hu | (hp << 16);
        return;
    }
    const float* W; float* ws; float* wb; u32* Ah;
    const float* gg; const float* bb; int m, mdst; float extra = 0.f;
    if (row < 256)      { W=Wq; ws=g_wsq;  wb=g_wbq;  Ah=g_Aq;  gg=gopt; bb=bopt; m=row;     mdst=m; }
    else if (row < 512) { W=Wk; ws=g_wskv; wb=g_wbkv; Ah=g_Akv; gg=gsar; bb=bsar; m=row-256; mdst=m; }
    else if (row < 768) { W=Wv; ws=g_wskv; wb=g_wbkv; Ah=g_Akv; gg=gsar; bb=bsar; m=row-512; mdst=m+256; }
    else {
        W=W1; ws=g_ws1; wb=g_wb1v; Ah=g_A1; gg=gffn; bb=bffn; m=row-768;
        extra = b1[m];
        if (m < FH) mdst = ((m>>3)<<4) + (m&7);
        else        { int mm = m-FH; mdst = ((mm>>3)<<4) + (mm&7) + 8; }
    }
    float w  = W[m*CC + c];
    float wg = w * gg[c];
    u32 hu = (u32)__half_as_ushort(__float2half_rn(wg));
    u32 hp = __shfl_xor_sync(0xffffffffu, hu, 1);
    if (!(c & 1)) Ah[mdst*128 + (c>>1)] = hu | (hp << 16);
    __shared__ float s1[256], s2[256];
    s1[c] = wg; s2[c] = w * bb[c];
    __syncthreads();
    for (int off = 128; off > 0; off >>= 1) {
        if (c < off) { s1[c] += s1[c+off]; s2[c] += s2[c+off]; }
        __syncthreads();
    }
    if (c == 0) { ws[mdst] = s1[0]; wb[mdst] = s2[0] + extra; }
}

// ---------------------------------------------------------------------------
// LN stats + fp16 conversion (both input tensors, one launch)
// ---------------------------------------------------------------------------
__global__ __launch_bounds__(512)
void ln_conv_kernel(const float* __restrict__ x0, const float* __restrict__ x1)
{
    const float* x  = blockIdx.y ? x1 : x0;
    float* mu = blockIdx.y ? g_mu_s : g_mu_o;
    float* rs = blockIdx.y ? g_rs_s : g_rs_o;
    u32* x16  = blockIdx.y ? g_s16 : g_o16;
    __shared__ float ssx[512], ssx2[512], ssy[512], ssy2[512];
    int tid = threadIdx.x;
    int pr = tid & 127, qd = tid >> 7;
    int p2 = blockIdx.x*128 + pr;
    int b = p2 >> 11, l2 = p2 & 2047;
    const float* base = x + (size_t)b*CC*LL + 2*l2;
    u32* oh = x16 + (size_t)b*CC*(LL/2) + l2;
    float sx=0.f, sx2=0.f, sy=0.f, sy2=0.f;
    int c0 = qd*64;
#pragma unroll 8
    for (int i = 0; i < 64; i++) {
        int c = c0 + i;
        float2 v = *(const float2*)(base + (size_t)c*LL);
        sx += v.x; sx2 = fmaf(v.x, v.x, sx2);
        sy += v.y; sy2 = fmaf(v.y, v.y, sy2);
        oh[(size_t)c*(LL/2)] = packf16(v.x, v.y);
    }
    ssx[tid]=sx; ssx2[tid]=sx2; ssy[tid]=sy; ssy2[tid]=sy2;
    __syncthreads();
    if (qd == 0) {
        float tx  = ssx[pr]  + ssx[pr+128]  + ssx[pr+256]  + ssx[pr+384];
        float tx2 = ssx2[pr] + ssx2[pr+128] + ssx2[pr+256] + ssx2[pr+384];
        float ty  = ssy[pr]  + ssy[pr+128]  + ssy[pr+256]  + ssy[pr+384];
        float ty2 = ssy2[pr] + ssy2[pr+128] + ssy2[pr+256] + ssy2[pr+384];
        float mx = tx*(1.f/CC), my = ty*(1.f/CC);
        int p = b*LL + 2*l2;
        mu[p]   = mx; rs[p]   = rsqrtf(fmaf(-mx, mx, tx2*(1.f/CC)) + 1e-5f);
        mu[p+1] = my; rs[p+1] = rsqrtf(fmaf(-my, my, ty2*(1.f/CC)) + 1e-5f);
    }
}

#define A_STR 144

// ---------------------------------------------------------------------------
// Fused Q+KV projection GEMM, 3-stage cp.async. grid (32, 6, BB).
// ---------------------------------------------------------------------------
__global__ __launch_bounds__(256, 2)
void gemm_qkv()
{
    constexpr int KD = 256, MT = 128, NT = 128;
    constexpr int B_STRc = NT*2 + 16;
    constexpr int BS = MT*A_STR;
    constexpr int STAGE = BS + 64*B_STRc;

    extern __shared__ __align__(128) char smem[];
    const u32 sbase = smem_u32(smem);

    int y = blockIdx.y;
    bool isq = (y < 2);
    const u32* Ah   = isq ? g_Aq  : g_Akv;
    const u32* Xp   = isq ? g_o16 : g_s16;
    u32* Y16        = isq ? g_q16 : g_kv16;
    const float* mu = isq ? g_mu_o : g_mu_s;
    const float* rs = isq ? g_rs_o : g_rs_s;
    const float* wsum = isq ? g_wsq : g_wskv;
    const float* wb   = isq ? g_wbq : g_wbkv;
    int md = isq ? 256 : 512;
    int m0 = (isq ? y : y - 2) * MT;

    int tid = threadIdx.x, lane = tid & 31, wid = tid >> 5;
    int n0 = blockIdx.x * NT, b = blockIdx.z;
    int wm = wid >> 2, wn = wid & 3;

    float acc[4][4][4];
#pragma unroll
    for (int i=0;i<4;i++)
#pragma unroll
        for (int j=0;j<4;j++)
#pragma unroll
            for (int r=0;r<4;r++) acc[i][j][r]=0.f;

    const u32* Xb = Xp + (size_t)b*KD*(LL/2) + (n0>>1);
    u32 a_lm_base = sbase + (u32)((wm*64 + (lane & 15)) * A_STR) + ((lane & 16) ? 16u : 0u);
    u32 b_lm_base = sbase + BS + (u32)((lane & 15) * B_STRc)
                  + (u32)((wn*32 + ((lane & 16) ? 8 : 0)) * 2);

#define ISSUEQ(st, kc) do { \
        u32 so = sbase + (u32)((st)*STAGE); \
        _Pragma("unroll") \
        for (int ii = tid; ii < MT*8; ii += 256) { \
            int row = ii >> 3, seg = ii & 7; \
            CP16(so + (u32)(row*A_STR + seg*16), \
                 Ah + (size_t)(m0+row)*(KD/2) + ((kc)>>1) + seg*4); \
        } \
        _Pragma("unroll") \
        for (int ii = tid; ii < 64*16; ii += 256) { \
            int row = ii >> 4, seg = ii & 15; \
            CP16(so + (u32)(BS + row*B_STRc + seg*16), \
                 Xb + (size_t)((kc)+row)*(LL/2) + seg*4); \
        } \
        CP_COMMIT(); \
    } while(0)

    ISSUEQ(0, 0);
    ISSUEQ(1, 64);
#pragma unroll 1
    for (int kc = 0; kc < KD; kc += 64) {
        int cur = (kc >> 6) % 3;
        if (kc + 128 < KD) { ISSUEQ((cur + 2) % 3, kc + 128); CP_WAIT(2); }
        else if (kc + 64 < KD) { CP_WAIT(1); }
        else { CP_WAIT(0); }
        __syncthreads();
        u32 so = (u32)(cur * STAGE);
#pragma unroll
        for (int ks = 0; ks < 64; ks += 16) {
            u32 af[4][4], bf[4][2];
            u32 ab = a_lm_base + so + (u32)(ks*2);
#pragma unroll
            for (int i = 0; i < 4; i++)
                LDSM_X4(af[i][0], af[i][1], af[i][2], af[i][3], ab + (u32)(i*16*A_STR));
            u32 bb0 = b_lm_base + so + (u32)(ks*B_STRc);
#pragma unroll
            for (int j2 = 0; j2 < 2; j2++)
                LDSM_X4_T(bf[j2*2][0], bf[j2*2][1], bf[j2*2+1][0], bf[j2*2+1][1], bb0 + (u32)(j2*32));
#pragma unroll
            for (int i = 0; i < 4; i++)
#pragma unroll
                for (int j = 0; j < 4; j++)
                    MMA_F16(acc[i][j], af[i], bf[j][0], bf[j][1]);
        }
        __syncthreads();
    }
#undef ISSUEQ

#pragma unroll
    for (int i = 0; i < 4; i++) {
        int r0 = m0 + wm*64 + i*16 + (lane >> 2);
        int r1 = r0 + 8;
        float ws0 = wsum[r0], wb0 = wb[r0];
        float ws1v = wsum[r1], wb1 = wb[r1];
#pragma unroll
        for (int j = 0; j < 4; j++) {
            int c0 = n0 + wn*32 + j*8 + 2*(lane & 3);
            int p0 = b*LL + c0;
            float2 m2 = *(const float2*)(mu + p0);
            float2 s2 = *(const float2*)(rs + p0);
            float o0x = s2.x*(acc[i][j][0] - m2.x*ws0) + wb0;
            float o0y = s2.y*(acc[i][j][1] - m2.y*ws0) + wb0;
            float o1x = s2.x*(acc[i][j][2] - m2.x*ws1v) + wb1;
            float o1y = s2.y*(acc[i][j][3] - m2.y*ws1v) + wb1;
            Y16[((size_t)b*md + r0)*(LL/2) + (c0>>1)] = packf16(o0x, o0y);
            Y16[((size_t)b*md + r1)*(LL/2) + (c0>>1)] = packf16(o1x, o1y);
        }
    }
}

// ---------------------------------------------------------------------------
// General GEMM (modes 2/3), 3-stage cp.async. MT=128, NT=128.
// ---------------------------------------------------------------------------
template<int MODE, int KD, int MD, int MT, int NT>
__global__ __launch_bounds__(256, 2)
void gemm_mma(const u32* __restrict__ Ah,
              const u32* __restrict__ Xp,
              void* __restrict__ Yv,
              const float* __restrict__ mu, const float* __restrict__ rs,
              const float* __restrict__ wsum, const float* __restrict__ wb,
              const void* __restrict__ res, const float* __restrict__ bias)
{
    constexpr int B_STRc = NT*2 + 16;
    constexpr int BS = MT*A_STR;
    constexpr int STAGE = MT*A_STR + 64*B_STRc;
    constexpr int WN = (MT == 128) ? 4 : 2;
    constexpr int BSEG = NT/8;

    extern __shared__ __align__(128) char smem[];
    const u32 sbase = smem_u32(smem);

    int tid = threadIdx.x, lane = tid & 31, wid = tid >> 5;
    int n0 = blockIdx.x * NT, m0 = blockIdx.y * MT, b = blockIdx.z;
    int wm = wid / WN, wn = wid % WN;

    float acc[4][4][4];
#pragma unroll
    for (int i=0;i<4;i++)
#pragma unroll
        for (int j=0;j<4;j++)
#pragma unroll
            for (int r=0;r<4;r++) acc[i][j][r]=0.f;

    const u32* Xb = Xp + (size_t)b*KD*(LL/2) + (n0>>1);

    u32 a_lm_base = sbase + (u32)((wm*64 + (lane & 15)) * A_STR) + ((lane & 16) ? 16u : 0u);
    u32 b_lm_base = sbase + BS + (u32)((lane & 15) * B_STRc)
                  + (u32)((wn*32 + ((lane & 16) ? 8 : 0)) * 2);

#define ISSUE(st, kc) do { \
        u32 so = sbase + (u32)((st)*STAGE); \
        _Pragma("unroll") \
        for (int ii = tid; ii < MT*8; ii += 256) { \
            int row = ii >> 3, seg = ii & 7; \
            CP16(so + (u32)(row*A_STR + seg*16), \
                 Ah + (size_t)(m0+row)*(KD/2) + ((kc)>>1) + seg*4); \
        } \
        _Pragma("unroll") \
        for (int ii = tid; ii < 64*BSEG; ii += 256) { \
            int row = ii / BSEG, seg = ii % BSEG; \
            CP16(so + (u32)(BS + row*B_STRc + seg*16), \
                 Xb + (size_t)((kc)+row)*(LL/2) + seg*4); \
        } \
        CP_COMMIT(); \
    } while(0)

    ISSUE(0, 0);
    ISSUE(1, 64);

#pragma unroll 1
    for (int kc = 0; kc < KD; kc += 64) {
        int cur = (kc >> 6) % 3;
        if (kc + 128 < KD) { ISSUE((cur + 2) % 3, kc + 128); CP_WAIT(2); }
        else if (kc + 64 < KD) { CP_WAIT(1); }
        else { CP_WAIT(0); }
        __syncthreads();
        u32 so = (u32)(cur * STAGE);
#pragma unroll
        for (int ks = 0; ks < 64; ks += 16) {
            u32 af[4][4], bf[4][2];
            u32 ab = a_lm_base + so + (u32)(ks*2);
#pragma unroll
            for (int i = 0; i < 4; i++)
                LDSM_X4(af[i][0], af[i][1], af[i][2], af[i][3], ab + (u32)(i*16*A_STR));
            u32 bb0 = b_lm_base + so + (u32)(ks*B_STRc);
#pragma unroll
            for (int j2 = 0; j2 < 2; j2++)
                LDSM_X4_T(bf[j2*2][0], bf[j2*2][1], bf[j2*2+1][0], bf[j2*2+1][1], bb0 + (u32)(j2*32));
#pragma unroll
            for (int i = 0; i < 4; i++)
#pragma unroll
                for (int j = 0; j < 4; j++)
                    MMA_F16(acc[i][j], af[i], bf[j][0], bf[j][1]);
        }
        __syncthreads();
    }
#undef ISSUE

    float* Y = (float*)Yv;
#pragma unroll
    for (int i = 0; i < 4; i++) {
        int r0 = m0 + wm*64 + i*16 + (lane >> 2);
        int r1 = r0 + 8;
        if (MODE == 3) {
            int t = ((r0 >> 4) << 3) + (r0 & 7);
            float ws1 = wsum[r0], wb1 = wb[r0];
            float ws2 = wsum[r1], wb2 = wb[r1];
#pragma unroll
            for (int j = 0; j < 4; j++) {
                int c0 = n0 + wn*32 + j*8 + 2*(lane & 3);
                int p0 = b*LL + c0;
                float2 m2 = *(const float2*)(mu + p0);
                float2 s2 = *(const float2*)(rs + p0);
                float e1x = s2.x*(acc[i][j][0] - m2.x*ws1) + wb1;
                float e1y = s2.y*(acc[i][j][1] - m2.y*ws1) + wb1;
                float e2x = s2.x*(acc[i][j][2] - m2.x*ws2) + wb2;
                float e2y = s2.y*(acc[i][j][3] - m2.y*ws2) + wb2;
                g_hg[((size_t)b*FH + t)*(LL/2) + (c0 >> 1)] = packf16(e1x*e2x, e1y*e2y);
            }
        } else { // MODE 2
            const u32* r16 = (const u32*)res;
            float bv0 = bias[r0], bv1 = bias[r1];
#pragma unroll
            for (int j = 0; j < 4; j++) {
                int c0 = n0 + wn*32 + j*8 + 2*(lane & 3);
                float2 a0 = unpackf16(r16[((size_t)b*MD + r0)*(LL/2) + (c0>>1)]);
                float2 a1 = unpackf16(r16[((size_t)b*MD + r1)*(LL/2) + (c0>>1)]);
                float* y0 = Y + (size_t)b*MD*LL + (size_t)r0*LL + c0;
                float* y1 = Y + (size_t)b*MD*LL + (size_t)r1*LL + c0;
                *(float2*)y0 = make_float2(acc[i][j][0] + bv0 + a0.x, acc[i][j][1] + bv0 + a0.y);
                *(float2*)y1 = make_float2(acc[i][j][2] + bv1 + a1.x, acc[i][j][3] + bv1 + a1.y);
            }
        }
    }
}

// ---------------------------------------------------------------------------
// Fused Wo GEMM with inline A@V B-tile construction + residual + LN stats.
// ---------------------------------------------------------------------------
#define WO_BSTR 144
#define WO_A    (256*WO_BSTR)
#define WO_STAGE (256*A_STR)
#define WO_SMEM (WO_A + 2*WO_STAGE)

__global__ __launch_bounds__(256, 2)
void gemm_wo_av(const float* __restrict__ res)
{
    extern __shared__ __align__(128) char smem[];
    const u32 sbase = smem_u32(smem);
    int tid = threadIdx.x, lane = tid & 31, wid = tid >> 5;
    int n0 = blockIdx.x * 64, b = blockIdx.z;

    const u32* Vb = g_kv16 + ((size_t)b*2*CC + CC)*(LL/2) + (n0>>1);
#pragma unroll
    for (int ii = tid; ii < 256*8; ii += 256) {
        int row = ii >> 3, seg = ii & 7;
        CP16(sbase + (u32)(row*WO_BSTR + seg*16), Vb + (size_t)row*(LL/2) + seg*4);
    }
    CP_COMMIT();
#pragma unroll
    for (int ii = tid; ii < 256*8; ii += 256) {
        int row = ii >> 3, seg = ii & 7;
        CP16(sbase + (u32)(WO_A + row*A_STR + seg*16), g_Ao + (size_t)row*128 + seg*4);
    }
    CP_COMMIT();
    CP_WAIT(1);
    __syncthreads();

    {
        float av[2][8][4];
#pragma unroll
        for (int i=0;i<2;i++)
#pragma unroll
            for (int j=0;j<8;j++)
#pragma unroll
                for (int r=0;r<4;r++) av[i][j][r]=0.f;
        const u32* Ab = g_A16 + (size_t)(b*NHH + wid)*512;
        int r0 = lane >> 2, cq = lane & 3;
#pragma unroll
        for (int s = 0; s < 2; s++) {
            u32 af[2][4];
#pragma unroll
            for (int i = 0; i < 2; i++) {
                af[i][0] = Ab[(i*16 + r0     )*16 + s*8 + cq];
                af[i][1] = Ab[(i*16 + r0 + 8 )*16 + s*8 + cq];
                af[i][2] = Ab[(i*16 + r0     )*16 + s*8 + cq + 4];
                af[i][3] = Ab[(i*16 + r0 + 8 )*16 + s*8 + cq + 4];
            }
            u32 vrow = sbase + (u32)((wid*32 + s*16 + (lane & 15))*WO_BSTR)
                     + ((lane & 16) ? 16u : 0u);
            u32 bf[8][2];
#pragma unroll
            for (int j2 = 0; j2 < 4; j2++)
                LDSM_X4_T(bf[j2*2][0], bf[j2*2][1], bf[j2*2+1][0], bf[j2*2+1][1],
                          vrow + (u32)(j2*32));
#pragma unroll
            for (int i = 0; i < 2; i++)
#pragma unroll
                for (int j = 0; j < 8; j++)
                    MMA_F16(av[i][j], af[i], bf[j][0], bf[j][1]);
        }
#pragma unroll
        for (int i = 0; i < 2; i++) {
            int row = wid*32 + i*16 + (lane >> 2);
#pragma unroll
            for (int j = 0; j < 8; j++) {
                int c0 = j*8 + 2*(lane & 3);
                *(u32*)(smem + row*WO_BSTR + c0*2)     = packf16(av[i][j][0], av[i][j][1]);
                *(u32*)(smem + (row+8)*WO_BSTR + c0*2) = packf16(av[i][j][2], av[i][j][3]);
            }
        }
    }
    __syncthreads();

    int wm = wid >> 1, wn = wid & 1;
    float acc[4][4][4];
#pragma unroll
    for (int i=0;i<4;i++)
#pragma unroll
        for (int j=0;j<4;j++)
#pragma unroll
            for (int r=0;r<4;r++) acc[i][j][r]=0.f;

    u32 a_lm_base = sbase + (u32)(WO_A + (wm*64 + (lane & 15)) * A_STR) + ((lane & 16) ? 16u : 0u);
    u32 b_lm_base = sbase + (u32)((lane & 15) * WO_BSTR)
                  + (u32)((wn*32 + ((lane & 16) ? 8 : 0)) * 2);

#pragma unroll 1
    for (int kc = 0; kc < 256; kc += 64) {
        int cur = (kc >> 6) & 1;
        if (kc + 64 < 256) {
            u32 so = sbase + (u32)(WO_A + (cur^1)*WO_STAGE);
#pragma unroll
            for (int ii = tid; ii < 256*8; ii += 256) {
                int row = ii >> 3, seg = ii & 7;
                CP16(so + (u32)(row*A_STR + seg*16),
                     g_Ao + (size_t)row*128 + ((kc+64)>>1) + seg*4);
            }
            CP_COMMIT();
            CP_WAIT(1);
        } else {
            CP_WAIT(0);
        }
        __syncthreads();
        u32 so = (u32)(cur * WO_STAGE);
#pragma unroll
        for (int ks = 0; ks < 64; ks += 16) {
            u32 af[4][4], bf[4][2];
            u32 ab = a_lm_base + so + (u32)(ks*2);
#pragma unroll
            for (int i = 0; i < 4; i++)
                LDSM_X4(af[i][0], af[i][1], af[i][2], af[i][3], ab + (u32)(i*16*A_STR));
            u32 bb0 = b_lm_base + (u32)((kc + ks)*WO_BSTR);
#pragma unroll
            for (int j2 = 0; j2 < 2; j2++)
                LDSM_X4_T(bf[j2*2][0], bf[j2*2][1], bf[j2*2+1][0], bf[j2*2+1][1], bb0 + (u32)(j2*32));
#pragma unroll
            for (int i = 0; i < 4; i++)
#pragma unroll
                for (int j = 0; j < 4; j++)
                    MMA_F16(acc[i][j], af[i], bf[j][0], bf[j][1]);
        }
        __syncthreads();
    }

    float cs[4][4];
#pragma unroll
    for (int j=0;j<4;j++)
#pragma unroll
        for (int k=0;k<4;k++) cs[j][k]=0.f;
#pragma unroll
    for (int i = 0; i < 4; i++) {
        int r0 = wm*64 + i*16 + (lane >> 2);
        int r1 = r0 + 8;
#pragma unroll
        for (int j = 0; j < 4; j++) {
            int c0 = n0 + wn*32 + j*8 + 2*(lane & 3);
            const float* q0 = res + (size_t)b*CC*LL + (size_t)r0*LL + c0;
            const float* q1 = res + (size_t)b*CC*LL + (size_t)r1*LL + c0;
            float2 a0 = *(const float2*)q0, a1 = *(const float2*)q1;
            float y00 = acc[i][j][0] + a0.x, y01 = acc[i][j][1] + a0.y;
            float y10 = acc[i][j][2] + a1.x, y11 = acc[i][j][3] + a1.y;
            g_x16[((size_t)b*CC + r0)*(LL/2) + (c0>>1)] = packf16(y00, y01);
            g_x16[((size_t)b*CC + r1)*(LL/2) + (c0>>1)] = packf16(y10, y11);
            cs[j][0] += y00 + y10;
            cs[j][1] += y00*y00 + y10*y10;
            cs[j][2] += y01 + y11;
            cs[j][3] += y01*y01 + y11*y11;
        }
    }
    {
        float4 (*red)[32] = (float4(*)[32])smem;
#pragma unroll
        for (int j = 0; j < 4; j++)
#pragma unroll
            for (int o = 4; o < 32; o <<= 1) {
                cs[j][0] += __shfl_xor_sync(0xffffffffu, cs[j][0], o);
                cs[j][1] += __shfl_xor_sync(0xffffffffu, cs[j][1], o);
                cs[j][2] += __shfl_xor_sync(0xffffffffu, cs[j][2], o);
                cs[j][3] += __shfl_xor_sync(0xffffffffu, cs[j][3], o);
            }
        if (lane < 4) {
#pragma unroll
            for (int j = 0; j < 4; j++) {
                int cp = wn*16 + j*4 + lane;
                red[wm][cp] = make_float4(cs[j][0], cs[j][1], cs[j][2], cs[j][3]);
            }
        }
        __syncthreads();
        if (tid < 32) {
            float4 t0 = red[0][tid], t1 = red[1][tid], t2 = red[2][tid], t3 = red[3][tid];
            float sx  = t0.x+t1.x+t2.x+t3.x;
            float sx2 = t0.y+t1.y+t2.y+t3.y;
            float sy  = t0.z+t1.z+t2.z+t3.z;
            float sy2 = t0.w+t1.w+t2.w+t3.w;
            float mx = sx*(1.f/CC), my = sy*(1.f/CC);
            int p = b*LL + n0 + 2*tid;
            g_mu_x[p]   = mx; g_rs_x[p]   = rsqrtf(fmaf(-mx, mx, sx2*(1.f/CC)) + 1e-5f);
            g_mu_x[p+1] = my; g_rs_x[p+1] = rsqrtf(fmaf(-my, my, sy2*(1.f/CC)) + 1e-5f);
        }
    }
}

// ---------------------------------------------------------------------------
// Attention S via mma.sync + softmax -> packed fp16 A
// ---------------------------------------------------------------------------
#define QSTR 528
#define ATILE (32*QSTR)
#define ASTAGE (2*ATILE)
#define AS_SMEM (2*ASTAGE)

__global__ __launch_bounds__(256, 2)
void attn_s_kernel()
{
    extern __shared__ __align__(128) char smem[];
    const u32 sbase = smem_u32(smem);
    int bh = blockIdx.x, sp = blockIdx.y;
    int b = bh >> 3, h = bh & 7;
    int tid = threadIdx.x, lane = tid & 31, wid = tid >> 5;
    const u32* qp = g_q16  + ((size_t)b*CC   + h*HCC)*(LL/2) + sp*1024;
    const u32* kp = g_kv16 + ((size_t)b*2*CC + h*HCC)*(LL/2) + sp*1024;

    float acc[2][4][4];
#pragma unroll
    for (int i=0;i<2;i++)
#pragma unroll
        for (int j=0;j<4;j++)
#pragma unroll
            for (int r=0;r<4;r++) acc[i][j][r]=0.f;

#define ISSUEA(st, ch) do { \
        u32 so = sbase + (u32)((st)*ASTAGE); \
        _Pragma("unroll") \
        for (int ii = tid; ii < 1024; ii += 256) { \
            int row = ii >> 5, seg = ii & 31; \
            CP16(so + (u32)(row*QSTR + seg*16), \
                 qp + (size_t)row*(LL/2) + (ch)*128 + seg*4); \
            CP16(so + (u32)(ATILE + row*QSTR + seg*16), \
                 kp + (size_t)row*(LL/2) + (ch)*128 + seg*4); \
        } \
        CP_COMMIT(); \
    } while(0)

    ISSUEA(0, 0);
    u32 woff = (u32)(wid * 64);
#pragma unroll 1
    for (int ch = 0; ch < 8; ch++) {
        int cur = ch & 1;
        if (ch + 1 < 8) { ISSUEA(cur ^ 1, ch + 1); CP_WAIT(1); }
        else            { CP_WAIT(0); }
        __syncthreads();
        u32 qb = sbase + (u32)(cur*ASTAGE);
        u32 kb = qb + ATILE;
#pragma unroll
        for (int s = 0; s < 2; s++) {
            u32 koff = woff + (u32)(s*32);
            u32 af[2][4], bf[4][2];
            u32 aaddr = qb + (u32)((lane & 15)*QSTR) + ((lane & 16) ? 16u : 0u) + koff;
            LDSM_X4(af[0][0], af[0][1], af[0][2], af[0][3], aaddr);
            LDSM_X4(af[1][0], af[1][1], af[1][2], af[1][3], aaddr + (u32)(16*QSTR));
            u32 baddr = kb + (u32)(((lane & 7) + ((lane & 16) ? 8 : 0))*QSTR)
                      + ((lane & 8) ? 16u : 0u) + koff;
            LDSM_X4(bf[0][0], bf[0][1], bf[1][0], bf[1][1], baddr);
            LDSM_X4(bf[2][0], bf[2][1], bf[3][0], bf[3][1], baddr + (u32)(16*QSTR));
#pragma unroll
            for (int i = 0; i < 2; i++)
#pragma unroll
                for (int j = 0; j < 4; j++)
                    MMA_F16(acc[i][j], af[i], bf[j][0], bf[j][1]);
        }
        __syncthreads();
    }
#undef ISSUEA

    float* part = (float*)smem;
#pragma unroll
    for (int i = 0; i < 2; i++)
#pragma unroll
        for (int j = 0; j < 4; j++)
#pragma unroll
            for (int r = 0; r < 4; r++) {
                int row = i*16 + (lane >> 2) + ((r & 2) ? 8 : 0);
                int col = j*8 + (lane & 3)*2 + (r & 1);
                part[wid*1024 + row*32 + col] = acc[i][j][r];
            }
    __syncthreads();
    float* out = g_Sp + ((size_t)bh*NSP + sp)*1024;
#pragma unroll
    for (int e = tid; e < 1024; e += 256) {
        float s = 0.f;
#pragma unroll
        for (int w = 0; w < 8; w++) s += part[w*1024 + e];
        out[e] = s;
    }
}

__global__ void attn_softmax_kernel()
{
    int bh = blockIdx.x, t = threadIdx.x;
    const float* sp = g_Sp + (size_t)bh*NSP*1024 + t;
    float s = sp[0] + sp[1024];
    s *= 0.17677669529663687f;
    float mx = s;
#pragma unroll
    for (int o = 16; o > 0; o >>= 1) mx = fmaxf(mx, __shfl_xor_sync(0xffffffffu, mx, o));
    float e = expf(s - mx);
    float sum = e;
#pragma unroll
    for (int o = 16; o > 0; o >>= 1) sum += __shfl_xor_sync(0xffffffffu, sum, o);
    float a = e / sum;
    float ap = __shfl_xor_sync(0xffffffffu, a, 1);
    int c = t >> 5, d = t & 31;
    if (!(d & 1)) g_A16[(size_t)bh*512 + c*16 + (d >> 1)] = packf16(a, ap);
}

// ---------------------------------------------------------------------------
// Launcher
// ---------------------------------------------------------------------------
#define GS3 (3*(128*A_STR + 64*(128*2+16)))   // 107520

extern "C" void kernel_launch(void* const* d_in, const int* in_sizes, int n_in,
                              void* d_out, int out_size)
{
    (void)in_sizes; (void)n_in; (void)out_size;
    const float* optical = (const float*)d_in[0];
    const float* sar     = (const float*)d_in[1];
    const float* gopt    = (const float*)d_in[2];
    const float* bopt    = (const float*)d_in[3];
    const float* gsar    = (const float*)d_in[4];
    const float* bsar    = (const float*)d_in[5];
    const float* Wq      = (const float*)d_in[6];
    const float* Wk      = (const float*)d_in[7];
    const float* Wv      = (const float*)d_in[8];
    const float* Wo      = (const float*)d_in[9];
    const float* gffn    = (const float*)d_in[10];
    const float* bffn    = (const float*)d_in[11];
    const float* W1      = (const float*)d_in[12];
    const float* b1      = (const float*)d_in[13];
    const float* W2      = (const float*)d_in[14];
    const float* b2      = (const float*)d_in[15];
    float* out = (float*)d_out;

    float *p_ws1,*p_wb1,*p_mu_x,*p_rs_x;
    u32 *p_A1,*p_A2,*p_x16,*p_hg;
    cudaGetSymbolAddress((void**)&p_ws1, g_ws1);     cudaGetSymbolAddress((void**)&p_wb1, g_wb1v);
    cudaGetSymbolAddress((void**)&p_mu_x, g_mu_x);   cudaGetSymbolAddress((void**)&p_rs_x, g_rs_x);
    cudaGetSymbolAddress((void**)&p_A1, g_A1);       cudaGetSymbolAddress((void**)&p_A2, g_A2);
    cudaGetSymbolAddress((void**)&p_x16, g_x16);     cudaGetSymbolAddress((void**)&p_hg, g_hg);

    cudaFuncSetAttribute((void*)gemm_qkv,                    cudaFuncAttributeMaxDynamicSharedMemorySize, GS3);
    cudaFuncSetAttribute((void*)gemm_wo_av,                  cudaFuncAttributeMaxDynamicSharedMemorySize, WO_SMEM);
    cudaFuncSetAttribute((void*)gemm_mma<3,256,FH2,128,128>, cudaFuncAttributeMaxDynamicSharedMemorySize, GS3);
    cudaFuncSetAttribute((void*)gemm_mma<2,512,256,128,128>, cudaFuncAttributeMaxDynamicSharedMemorySize, GS3);
    cudaFuncSetAttribute((void*)attn_s_kernel,               cudaFuncAttributeMaxDynamicSharedMemorySize, AS_SMEM);

    // 1) weight prep (one launch)
    prep_fold<<<2560, 256>>>(Wq, Wk, Wv, W1, Wo, W2,
                             gopt, bopt, gsar, bsar, gffn, bffn, b1);

    // 2) LN stats + fp16 conversion (both inputs, one launch)
    ln_conv_kernel<<<dim3((NPIX/2)/128, 2), 512>>>(optical, sar);

    // 3) fused Q + K/V projections -> fp16 (3-stage pipeline)
    gemm_qkv<<<dim3(32, 6, BB), 256, GS3>>>();

    // 4) channel attention: MMA partial S (2 L-splits), softmax -> fp16 A
    attn_s_kernel<<<dim3(BB*NHH, NSP), 256, AS_SMEM>>>();
    attn_softmax_kernel<<<BB*NHH, 1024>>>();

    // 5) Wo GEMM with inline A@V + residual(optical) + LN stats -> x16
    gemm_wo_av<<<dim3(64, 1, BB), 256, WO_SMEM>>>(optical);

    // 6) W1 (LN+b1 folded, row-paired) + fused SimpleGate -> hg (3-stage)
    gemm_mma<3,256,FH2,128,128><<<dim3(32,8,BB),256,GS3>>>(p_A1, p_x16, (void*)0, p_mu_x, p_rs_x, p_ws1, p_wb1, 0, 0);

    // 7) W2 + b2 + residual(x16) -> out fp32 (3-stage)
    gemm_mma<2,512,256,128,128><<<dim3(32,2,BB),256,GS3>>>(p_A2, p_hg, out, 0, 0, 0, 0, p_x16, b2);
}

// round 16
// speedup vs baseline: 1.0194x; 1.0194x over previous
#include <cuda_runtime.h>
#include <cuda_fp16.h>

typedef unsigned int u32;
typedef unsigned long long u64;

#define BB   16
#define CC   256
#define LL   4096
#define NHH  8
#define HCC  32
#define FH   512
#define FH2  1024
#define NPIX (BB*LL)
#define NSP  2

// ---------------------------------------------------------------------------
// Scratch
// ---------------------------------------------------------------------------
__device__ float g_wsq[CC],  g_wbq[CC];
__device__ float g_wskv[2*CC], g_wbkv[2*CC];
__device__ float g_ws1[FH2], g_wb1v[FH2];
__device__ float g_mu_o[NPIX], g_rs_o[NPIX];
__device__ float g_mu_s[NPIX], g_rs_s[NPIX];
__device__ float g_mu_x[NPIX], g_rs_x[NPIX];
__device__ __align__(128) u32 g_Aq[CC*128];
__device__ __align__(128) u32 g_Akv[2*CC*128];
__device__ __align__(128) u32 g_A1[FH2*128];
__device__ __align__(128) u32 g_Ao[CC*128];
__device__ __align__(128) u32 g_A2[CC*256];
__device__ __align__(128) u32 g_o16[BB*CC*(LL/2)];
__device__ __align__(128) u32 g_s16[BB*CC*(LL/2)];
__device__ __align__(128) u32 g_q16[BB*CC*(LL/2)];
__device__ __align__(128) u32 g_kv16[BB*2*CC*(LL/2)];
__device__ __align__(128) u32 g_x16[BB*CC*(LL/2)];
__device__ __align__(128) u32 g_hg[BB*FH*(LL/2)];
__device__ __align__(128) float g_Sp[BB*NHH*NSP*HCC*HCC];
__device__ __align__(128) u32 g_A16[BB*NHH*HCC*(HCC/2)];

// ---------------------------------------------------------------------------
// PTX helpers
// ---------------------------------------------------------------------------
__device__ __forceinline__ u32 smem_u32(const void* p) {
    u32 a;
    asm("{ .reg .u64 t; cvta.to.shared.u64 t, %1; cvt.u32.u64 %0, t; }" : "=r"(a) : "l"(p));
    return a;
}
#define LDSM_X4(r0,r1,r2,r3,addr) \
    asm volatile("ldmatrix.sync.aligned.m8n8.x4.shared.b16 {%0,%1,%2,%3}, [%4];" \
        : "=r"(r0),"=r"(r1),"=r"(r2),"=r"(r3) : "r"(addr))
#define LDSM_X4_T(r0,r1,r2,r3,addr) \
    asm volatile("ldmatrix.sync.aligned.m8n8.x4.trans.shared.b16 {%0,%1,%2,%3}, [%4];" \
        : "=r"(r0),"=r"(r1),"=r"(r2),"=r"(r3) : "r"(addr))
#define MMA_F16(d, a, b0, b1) \
    asm volatile("mma.sync.aligned.m16n8k16.row.col.f32.f16.f16.f32 " \
        "{%0,%1,%2,%3}, {%4,%5,%6,%7}, {%8,%9}, {%0,%1,%2,%3};" \
        : "+f"((d)[0]),"+f"((d)[1]),"+f"((d)[2]),"+f"((d)[3]) \
        : "r"((a)[0]),"r"((a)[1]),"r"((a)[2]),"r"((a)[3]), "r"(b0),"r"(b1))
#define CP16(dst, src) \
    asm volatile("cp.async.cg.shared.global [%0], [%1], 16;" \
        :: "r"(dst), "l"(src) : "memory")
#define CP_COMMIT() asm volatile("cp.async.commit_group;" ::: "memory")
#define CP_WAIT(n)  asm volatile("cp.async.wait_group %0;" :: "n"(n) : "memory")

__device__ __forceinline__ u32 packf16(float a, float b) {
    __half2 h = __floats2half2_rn(a, b);
    return *(u32*)&h;
}
__device__ __forceinline__ float2 unpackf16(u32 w) {
    __half2 h = *(__half2*)&w;
    return __half22float2(h);
}

// ---------------------------------------------------------------------------
// Combined prep + LN/conv kernel, 512 threads.
// blocks [0,256): LN optical ; [256,512): LN sar ;
// blocks [512,1792): weight prep, 2 rows per block (rows 0..2559).
// ---------------------------------------------------------------------------
__global__ __launch_bounds__(512)
void prep_ln_kernel(const float* __restrict__ optical, const float* __restrict__ sar,
                    const float* __restrict__ Wq, const float* __restrict__ Wk,
                    const float* __restrict__ Wv, const float* __restrict__ W1,
                    const float* __restrict__ Wo, const float* __restrict__ W2,
                    const float* __restrict__ gopt, const float* __restrict__ bopt,
                    const float* __restrict__ gsar, const float* __restrict__ bsar,
                    const float* __restrict__ gffn, const float* __restrict__ bffn,
                    const float* __restrict__ b1)
{
    int blk = blockIdx.x;
    int tid = threadIdx.x;
    if (blk < 512) {
        // ---- LN stats + fp16 conversion
        int which = blk >> 8;          // 0: optical, 1: sar
        const float* x  = which ? sar : optical;
        float* mu = which ? g_mu_s : g_mu_o;
        float* rs = which ? g_rs_s : g_rs_o;
        u32* x16  = which ? g_s16 : g_o16;
        __shared__ float ssx[512], ssx2[512], ssy[512], ssy2[512];
        int pr = tid & 127, qd = tid >> 7;
        int p2 = (blk & 255)*128 + pr;
        int b = p2 >> 11, l2 = p2 & 2047;
        const float* base = x + (size_t)b*CC*LL + 2*l2;
        u32* oh = x16 + (size_t)b*CC*(LL/2) + l2;
        float sx=0.f, sx2=0.f, sy=0.f, sy2=0.f;
        int c0 = qd*64;
#pragma unroll 8
        for (int i = 0; i < 64; i++) {
            int c = c0 + i;
            float2 v = *(const float2*)(base + (size_t)c*LL);
            sx += v.x; sx2 = fmaf(v.x, v.x, sx2);
            sy += v.y; sy2 = fmaf(v.y, v.y, sy2);
            oh[(size_t)c*(LL/2)] = packf16(v.x, v.y);
        }
        ssx[tid]=sx; ssx2[tid]=sx2; ssy[tid]=sy; ssy2[tid]=sy2;
        __syncthreads();
        if (qd == 0) {
            float tx  = ssx[pr]  + ssx[pr+128]  + ssx[pr+256]  + ssx[pr+384];
            float tx2 = ssx2[pr] + ssx2[pr+128] + ssx2[pr+256] + ssx2[pr+384];
            float ty  = ssy[pr]  + ssy[pr+128]  + ssy[pr+256]  + ssy[pr+384];
            float ty2 = ssy2[pr] + ssy2[pr+128] + ssy2[pr+256] + ssy2[pr+384];
            float mx = tx*(1.f/CC), my = ty*(1.f/CC);
            int p = b*LL + 2*l2;
            mu[p]   = mx; rs[p]   = rsqrtf(fmaf(-mx, mx, tx2*(1.f/CC)) + 1e-5f);
            mu[p+1] = my; rs[p+1] = rsqrtf(fmaf(-my, my, ty2*(1.f/CC)) + 1e-5f);
        }
        return;
    }
    // ---- weight prep: rows (blk-512)*2 + (tid>>8)
    int row = (blk - 512)*2 + (tid >> 8);
    int c   = tid & 255;
    if (row >= 1792) {
        // plain fp16 pack (Wo, W2)
        float w; u32* dst; int di;
        if (row < 2048) {
            int m = row - 1792;
            w = Wo[m*CC + c];
            dst = g_Ao; di = m*128 + (c>>1);
        } else {
            int r2 = row - 2048;
            int m = r2 >> 1, half = r2 & 1;
            int cg = half*256 + c;
            w = W2[m*512 + cg];
            dst = g_A2; di = m*256 + (cg>>1);
        }
        u32 hu = (u32)__half_as_ushort(__float2half_rn(w));
        u32 hp = __shfl_xor_sync(0xffffffffu, hu, 1);
        if (!(c & 1)) dst[di] = hu | (hp << 16);
        return;
    }
    const float* W; float* ws; float* wb; u32* Ah;
    const float* gg; const float* bb; int m, mdst; float extra = 0.f;
    if (row < 256)      { W=Wq; ws=g_wsq;  wb=g_wbq;  Ah=g_Aq;  gg=gopt; bb=bopt; m=row;     mdst=m; }
    else if (row < 512) { W=Wk; ws=g_wskv; wb=g_wbkv; Ah=g_Akv; gg=gsar; bb=bsar; m=row-256; mdst=m; }
    else if (row < 768) { W=Wv; ws=g_wskv; wb=g_wbkv; Ah=g_Akv; gg=gsar; bb=bsar; m=row-512; mdst=m+256; }
    else {
        W=W1; ws=g_ws1; wb=g_wb1v; Ah=g_A1; gg=gffn; bb=bffn; m=row-768;
        extra = b1[m];
        if (m < FH) mdst = ((m>>3)<<4) + (m&7);
        else        { int mm = m-FH; mdst = ((mm>>3)<<4) + (mm&7) + 8; }
    }
    float w  = W[m*CC + c];
    float wg = w * gg[c];
    u32 hu = (u32)__half_as_ushort(__float2half_rn(wg));
    u32 hp = __shfl_xor_sync(0xffffffffu, hu, 1);
    if (!(c & 1)) Ah[mdst*128 + (c>>1)] = hu | (hp << 16);
    __shared__ float s1[512], s2[512];
    s1[tid] = wg; s2[tid] = w * bb[c];
    __syncthreads();
    for (int off = 128; off > 0; off >>= 1) {
        if ((tid & 255) < off) { s1[tid] += s1[tid+off]; s2[tid] += s2[tid+off]; }
        __syncthreads();
    }
    if (c == 0) { ws[mdst] = s1[tid]; wb[mdst] = s2[tid] + extra; }
}

#define A_STR 144

// ---------------------------------------------------------------------------
// Fused Q+KV projection GEMM, 2-stage cp.async. grid (32, 6, BB).
// ---------------------------------------------------------------------------
__global__ __launch_bounds__(256, 2)
void gemm_qkv()
{
    constexpr int KD = 256, MT = 128, NT = 128;
    constexpr int B_STRc = NT*2 + 16;
    constexpr int BS = MT*A_STR;
    constexpr int STAGE = BS + 64*B_STRc;

    extern __shared__ __align__(128) char smem[];
    const u32 sbase = smem_u32(smem);

    int y = blockIdx.y;
    bool isq = (y < 2);
    const u32* Ah   = isq ? g_Aq  : g_Akv;
    const u32* Xp   = isq ? g_o16 : g_s16;
    u32* Y16        = isq ? g_q16 : g_kv16;
    const float* mu = isq ? g_mu_o : g_mu_s;
    const float* rs = isq ? g_rs_o : g_rs_s;
    const float* wsum = isq ? g_wsq : g_wskv;
    const float* wb   = isq ? g_wbq : g_wbkv;
    int md = isq ? 256 : 512;
    int m0 = (isq ? y : y - 2) * MT;

    int tid = threadIdx.x, lane = tid & 31, wid = tid >> 5;
    int n0 = blockIdx.x * NT, b = blockIdx.z;
    int wm = wid >> 2, wn = wid & 3;

    float acc[4][4][4];
#pragma unroll
    for (int i=0;i<4;i++)
#pragma unroll
        for (int j=0;j<4;j++)
#pragma unroll
            for (int r=0;r<4;r++) acc[i][j][r]=0.f;

    const u32* Xb = Xp + (size_t)b*KD*(LL/2) + (n0>>1);
    u32 a_lm_base = sbase + (u32)((wm*64 + (lane & 15)) * A_STR) + ((lane & 16) ? 16u : 0u);
    u32 b_lm_base = sbase + BS + (u32)((lane & 15) * B_STRc)
                  + (u32)((wn*32 + ((lane & 16) ? 8 : 0)) * 2);

#define ISSUEQ(st, kc) do { \
        u32 so = sbase + (u32)((st)*STAGE); \
        _Pragma("unroll") \
        for (int ii = tid; ii < MT*8; ii += 256) { \
            int row = ii >> 3, seg = ii & 7; \
            CP16(so + (u32)(row*A_STR + seg*16), \
                 Ah + (size_t)(m0+row)*(KD/2) + ((kc)>>1) + seg*4); \
        } \
        _Pragma("unroll") \
        for (int ii = tid; ii < 64*16; ii += 256) { \
            int row = ii >> 4, seg = ii & 15; \
            CP16(so + (u32)(BS + row*B_STRc + seg*16), \
                 Xb + (size_t)((kc)+row)*(LL/2) + seg*4); \
        } \
        CP_COMMIT(); \
    } while(0)

    ISSUEQ(0, 0);
#pragma unroll 1
    for (int kc = 0; kc < KD; kc += 64) {
        int cur = (kc >> 6) & 1;
        if (kc + 64 < KD) { ISSUEQ(cur ^ 1, kc + 64); CP_WAIT(1); }
        else              { CP_WAIT(0); }
        __syncthreads();
        u32 so = (u32)(cur * STAGE);
#pragma unroll
        for (int ks = 0; ks < 64; ks += 16) {
            u32 af[4][4], bf[4][2];
            u32 ab = a_lm_base + so + (u32)(ks*2);
#pragma unroll
            for (int i = 0; i < 4; i++)
                LDSM_X4(af[i][0], af[i][1], af[i][2], af[i][3], ab + (u32)(i*16*A_STR));
            u32 bb0 = b_lm_base + so + (u32)(ks*B_STRc);
#pragma unroll
            for (int j2 = 0; j2 < 2; j2++)
                LDSM_X4_T(bf[j2*2][0], bf[j2*2][1], bf[j2*2+1][0], bf[j2*2+1][1], bb0 + (u32)(j2*32));
#pragma unroll
            for (int i = 0; i < 4; i++)
#pragma unroll
                for (int j = 0; j < 4; j++)
                    MMA_F16(acc[i][j], af[i], bf[j][0], bf[j][1]);
        }
        __syncthreads();
    }
#undef ISSUEQ

#pragma unroll
    for (int i = 0; i < 4; i++) {
        int r0 = m0 + wm*64 + i*16 + (lane >> 2);
        int r1 = r0 + 8;
        float ws0 = wsum[r0], wb0 = wb[r0];
        float ws1v = wsum[r1], wb1 = wb[r1];
#pragma unroll
        for (int j = 0; j < 4; j++) {
            int c0 = n0 + wn*32 + j*8 + 2*(lane & 3);
            int p0 = b*LL + c0;
            float2 m2 = *(const float2*)(mu + p0);
            float2 s2 = *(const float2*)(rs + p0);
            float o0x = s2.x*(acc[i][j][0] - m2.x*ws0) + wb0;
            float o0y = s2.y*(acc[i][j][1] - m2.y*ws0) + wb0;
            float o1x = s2.x*(acc[i][j][2] - m2.x*ws1v) + wb1;
            float o1y = s2.y*(acc[i][j][3] - m2.y*ws1v) + wb1;
            Y16[((size_t)b*md + r0)*(LL/2) + (c0>>1)] = packf16(o0x, o0y);
            Y16[((size_t)b*md + r1)*(LL/2) + (c0>>1)] = packf16(o1x, o1y);
        }
    }
}

// ---------------------------------------------------------------------------
// General GEMM (modes 2/3), 2-stage cp.async. MT=128, NT=128.
// ---------------------------------------------------------------------------
template<int MODE, int KD, int MD, int MT, int NT>
__global__ __launch_bounds__(256, 2)
void gemm_mma(const u32* __restrict__ Ah,
              const u32* __restrict__ Xp,
              void* __restrict__ Yv,
              const float* __restrict__ mu, const float* __restrict__ rs,
              const float* __restrict__ wsum, const float* __restrict__ wb,
              const void* __restrict__ res, const float* __restrict__ bias)
{
    constexpr int B_STRc = NT*2 + 16;
    constexpr int BS = MT*A_STR;
    constexpr int STAGE = MT*A_STR + 64*B_STRc;
    constexpr int WN = (MT == 128) ? 4 : 2;
    constexpr int BSEG = NT/8;

    extern __shared__ __align__(128) char smem[];
    const u32 sbase = smem_u32(smem);

    int tid = threadIdx.x, lane = tid & 31, wid = tid >> 5;
    int n0 = blockIdx.x * NT, m0 = blockIdx.y * MT, b = blockIdx.z;
    int wm = wid / WN, wn = wid % WN;

    float acc[4][4][4];
#pragma unroll
    for (int i=0;i<4;i++)
#pragma unroll
        for (int j=0;j<4;j++)
#pragma unroll
            for (int r=0;r<4;r++) acc[i][j][r]=0.f;

    const u32* Xb = Xp + (size_t)b*KD*(LL/2) + (n0>>1);

    u32 a_lm_base = sbase + (u32)((wm*64 + (lane & 15)) * A_STR) + ((lane & 16) ? 16u : 0u);
    u32 b_lm_base = sbase + BS + (u32)((lane & 15) * B_STRc)
                  + (u32)((wn*32 + ((lane & 16) ? 8 : 0)) * 2);

#define ISSUE(st, kc) do { \
        u32 so = sbase + (u32)((st)*STAGE); \
        _Pragma("unroll") \
        for (int ii = tid; ii < MT*8; ii += 256) { \
            int row = ii >> 3, seg = ii & 7; \
            CP16(so + (u32)(row*A_STR + seg*16), \
                 Ah + (size_t)(m0+row)*(KD/2) + ((kc)>>1) + seg*4); \
        } \
        _Pragma("unroll") \
        for (int ii = tid; ii < 64*BSEG; ii += 256) { \
            int row = ii / BSEG, seg = ii % BSEG; \
            CP16(so + (u32)(BS + row*B_STRc + seg*16), \
                 Xb + (size_t)((kc)+row)*(LL/2) + seg*4); \
        } \
        CP_COMMIT(); \
    } while(0)

    ISSUE(0, 0);

#pragma unroll 1
    for (int kc = 0; kc < KD; kc += 64) {
        int cur = (kc >> 6) & 1;
        if (kc + 64 < KD) { ISSUE(cur ^ 1, kc + 64); CP_WAIT(1); }
        else              { CP_WAIT(0); }
        __syncthreads();
        u32 so = (u32)(cur * STAGE);
#pragma unroll
        for (int ks = 0; ks < 64; ks += 16) {
            u32 af[4][4], bf[4][2];
            u32 ab = a_lm_base + so + (u32)(ks*2);
#pragma unroll
            for (int i = 0; i < 4; i++)
                LDSM_X4(af[i][0], af[i][1], af[i][2], af[i][3], ab + (u32)(i*16*A_STR));
            u32 bb0 = b_lm_base + so + (u32)(ks*B_STRc);
#pragma unroll
            for (int j2 = 0; j2 < 2; j2++)
                LDSM_X4_T(bf[j2*2][0], bf[j2*2][1], bf[j2*2+1][0], bf[j2*2+1][1], bb0 + (u32)(j2*32));
#pragma unroll
            for (int i = 0; i < 4; i++)
#pragma unroll
                for (int j = 0; j < 4; j++)
                    MMA_F16(acc[i][j], af[i], bf[j][0], bf[j][1]);
        }
        __syncthreads();
    }
#undef ISSUE

    float* Y = (float*)Yv;
#pragma unroll
    for (int i = 0; i < 4; i++) {
        int r0 = m0 + wm*64 + i*16 + (lane >> 2);
        int r1 = r0 + 8;
        if (MODE == 3) {
            int t = ((r0 >> 4) << 3) + (r0 & 7);
            float ws1 = wsum[r0], wb1 = wb[r0];
            float ws2 = wsum[r1], wb2 = wb[r1];
#pragma unroll
            for (int j = 0; j < 4; j++) {
                int c0 = n0 + wn*32 + j*8 + 2*(lane & 3);
                int p0 = b*LL + c0;
                float2 m2 = *(const float2*)(mu + p0);
                float2 s2 = *(const float2*)(rs + p0);
                float e1x = s2.x*(acc[i][j][0] - m2.x*ws1) + wb1;
                float e1y = s2.y*(acc[i][j][1] - m2.y*ws1) + wb1;
                float e2x = s2.x*(acc[i][j][2] - m2.x*ws2) + wb2;
                float e2y = s2.y*(acc[i][j][3] - m2.y*ws2) + wb2;
                g_hg[((size_t)b*FH + t)*(LL/2) + (c0 >> 1)] = packf16(e1x*e2x, e1y*e2y);
            }
        } else { // MODE 2
            const u32* r16 = (const u32*)res;
            float bv0 = bias[r0], bv1 = bias[r1];
#pragma unroll
            for (int j = 0; j < 4; j++) {
                int c0 = n0 + wn*32 + j*8 + 2*(lane & 3);
                float2 a0 = unpackf16(r16[((size_t)b*MD + r0)*(LL/2) + (c0>>1)]);
                float2 a1 = unpackf16(r16[((size_t)b*MD + r1)*(LL/2) + (c0>>1)]);
                float* y0 = Y + (size_t)b*MD*LL + (size_t)r0*LL + c0;
                float* y1 = Y + (size_t)b*MD*LL + (size_t)r1*LL + c0;
                *(float2*)y0 = make_float2(acc[i][j][0] + bv0 + a0.x, acc[i][j][1] + bv0 + a0.y);
                *(float2*)y1 = make_float2(acc[i][j][2] + bv1 + a1.x, acc[i][j][3] + bv1 + a1.y);
            }
        }
    }
}

// ---------------------------------------------------------------------------
// Fused Wo GEMM with inline A@V B-tile construction + residual + LN stats.
// ---------------------------------------------------------------------------
#define WO_BSTR 144
#define WO_A    (256*WO_BSTR)
#define WO_STAGE (256*A_STR)
#define WO_SMEM (WO_A + 2*WO_STAGE)

__global__ __launch_bounds__(256, 2)
void gemm_wo_av(const float* __restrict__ res)
{
    extern __shared__ __align__(128) char smem[];
    const u32 sbase = smem_u32(smem);
    int tid = threadIdx.x, lane = tid & 31, wid = tid >> 5;
    int n0 = blockIdx.x * 64, b = blockIdx.z;

    const u32* Vb = g_kv16 + ((size_t)b*2*CC + CC)*(LL/2) + (n0>>1);
#pragma unroll
    for (int ii = tid; ii < 256*8; ii += 256) {
        int row = ii >> 3, seg = ii & 7;
        CP16(sbase + (u32)(row*WO_BSTR + seg*16), Vb + (size_t)row*(LL/2) + seg*4);
    }
    CP_COMMIT();
#pragma unroll
    for (int ii = tid; ii < 256*8; ii += 256) {
        int row = ii >> 3, seg = ii & 7;
        CP16(sbase + (u32)(WO_A + row*A_STR + seg*16), g_Ao + (size_t)row*128 + seg*4);
    }
    CP_COMMIT();
    CP_WAIT(1);
    __syncthreads();

    {
        float av[2][8][4];
#pragma unroll
        for (int i=0;i<2;i++)
#pragma unroll
            for (int j=0;j<8;j++)
#pragma unroll
                for (int r=0;r<4;r++) av[i][j][r]=0.f;
        const u32* Ab = g_A16 + (size_t)(b*NHH + wid)*512;
        int r0 = lane >> 2, cq = lane & 3;
#pragma unroll
        for (int s = 0; s < 2; s++) {
            u32 af[2][4];
#pragma unroll
            for (int i = 0; i < 2; i++) {
                af[i][0] = Ab[(i*16 + r0     )*16 + s*8 + cq];
                af[i][1] = Ab[(i*16 + r0 + 8 )*16 + s*8 + cq];
                af[i][2] = Ab[(i*16 + r0     )*16 + s*8 + cq + 4];
                af[i][3] = Ab[(i*16 + r0 + 8 )*16 + s*8 + cq + 4];
            }
            u32 vrow = sbase + (u32)((wid*32 + s*16 + (lane & 15))*WO_BSTR)
                     + ((lane & 16) ? 16u : 0u);
            u32 bf[8][2];
#pragma unroll
            for (int j2 = 0; j2 < 4; j2++)
                LDSM_X4_T(bf[j2*2][0], bf[j2*2][1], bf[j2*2+1][0], bf[j2*2+1][1],
                          vrow + (u32)(j2*32));
#pragma unroll
            for (int i = 0; i < 2; i++)
#pragma unroll
                for (int j = 0; j < 8; j++)
                    MMA_F16(av[i][j], af[i], bf[j][0], bf[j][1]);
        }
#pragma unroll
        for (int i = 0; i < 2; i++) {
            int row = wid*32 + i*16 + (lane >> 2);
#pragma unroll
            for (int j = 0; j < 8; j++) {
                int c0 = j*8 + 2*(lane & 3);
                *(u32*)(smem + row*WO_BSTR + c0*2)     = packf16(av[i][j][0], av[i][j][1]);
                *(u32*)(smem + (row+8)*WO_BSTR + c0*2) = packf16(av[i][j][2], av[i][j][3]);
            }
        }
    }
    __syncthreads();

    int wm = wid >> 1, wn = wid & 1;
    float acc[4][4][4];
#pragma unroll
    for (int i=0;i<4;i++)
#pragma unroll
        for (int j=0;j<4;j++)
#pragma unroll
            for (int r=0;r<4;r++) acc[i][j][r]=0.f;

    u32 a_lm_base = sbase + (u32)(WO_A + (wm*64 + (lane & 15)) * A_STR) + ((lane & 16) ? 16u : 0u);
    u32 b_lm_base = sbase + (u32)((lane & 15) * WO_BSTR)
                  + (u32)((wn*32 + ((lane & 16) ? 8 : 0)) * 2);

#pragma unroll 1
    for (int kc = 0; kc < 256; kc += 64) {
        int cur = (kc >> 6) & 1;
        if (kc + 64 < 256) {
            u32 so = sbase + (u32)(WO_A + (cur^1)*WO_STAGE);
#pragma unroll
            for (int ii = tid; ii < 256*8; ii += 256) {
                int row = ii >> 3, seg = ii & 7;
                CP16(so + (u32)(row*A_STR + seg*16),
                     g_Ao + (size_t)row*128 + ((kc+64)>>1) + seg*4);
            }
            CP_COMMIT();
            CP_WAIT(1);
        } else {
            CP_WAIT(0);
        }
        __syncthreads();
        u32 so = (u32)(cur * WO_STAGE);
#pragma unroll
        for (int ks = 0; ks < 64; ks += 16) {
            u32 af[4][4], bf[4][2];
            u32 ab = a_lm_base + so + (u32)(ks*2);
#pragma unroll
            for (int i = 0; i < 4; i++)
                LDSM_X4(af[i][0], af[i][1], af[i][2], af[i][3], ab + (u32)(i*16*A_STR));
            u32 bb0 = b_lm_base + (u32)((kc + ks)*WO_BSTR);
#pragma unroll
            for (int j2 = 0; j2 < 2; j2++)
                LDSM_X4_T(bf[j2*2][0], bf[j2*2][1], bf[j2*2+1][0], bf[j2*2+1][1], bb0 + (u32)(j2*32));
#pragma unroll
            for (int i = 0; i < 4; i++)
#pragma unroll
                for (int j = 0; j < 4; j++)
                    MMA_F16(acc[i][j], af[i], bf[j][0], bf[j][1]);
        }
        __syncthreads();
    }

    float cs[4][4];
#pragma unroll
    for (int j=0;j<4;j++)
#pragma unroll
        for (int k=0;k<4;k++) cs[j][k]=0.f;
#pragma unroll
    for (int i = 0; i < 4; i++) {
        int r0 = wm*64 + i*16 + (lane >> 2);
        int r1 = r0 + 8;
#pragma unroll
        for (int j = 0; j < 4; j++) {
            int c0 = n0 + wn*32 + j*8 + 2*(lane & 3);
            const float* q0 = res + (size_t)b*CC*LL + (size_t)r0*LL + c0;
            const float* q1 = res + (size_t)b*CC*LL + (size_t)r1*LL + c0;
            float2 a0 = *(const float2*)q0, a1 = *(const float2*)q1;
            float y00 = acc[i][j][0] + a0.x, y01 = acc[i][j][1] + a0.y;
            float y10 = acc[i][j][2] + a1.x, y11 = acc[i][j][3] + a1.y;
            g_x16[((size_t)b*CC + r0)*(LL/2) + (c0>>1)] = packf16(y00, y01);
            g_x16[((size_t)b*CC + r1)*(LL/2) + (c0>>1)] = packf16(y10, y11);
            cs[j][0] += y00 + y10;
            cs[j][1] += y00*y00 + y10*y10;
            cs[j][2] += y01 + y11;
            cs[j][3] += y01*y01 + y11*y11;
        }
    }
    {
        float4 (*red)[32] = (float4(*)[32])smem;
#pragma unroll
        for (int j = 0; j < 4; j++)
#pragma unroll
            for (int o = 4; o < 32; o <<= 1) {
                cs[j][0] += __shfl_xor_sync(0xffffffffu, cs[j][0], o);
                cs[j][1] += __shfl_xor_sync(0xffffffffu, cs[j][1], o);
                cs[j][2] += __shfl_xor_sync(0xffffffffu, cs[j][2], o);
                cs[j][3] += __shfl_xor_sync(0xffffffffu, cs[j][3], o);
            }
        if (lane < 4) {
#pragma unroll
            for (int j = 0; j < 4; j++) {
                int cp = wn*16 + j*4 + lane;
                red[wm][cp] = make_float4(cs[j][0], cs[j][1], cs[j][2], cs[j][3]);
            }
        }
        __syncthreads();
        if (tid < 32) {
            float4 t0 = red[0][tid], t1 = red[1][tid], t2 = red[2][tid], t3 = red[3][tid];
            float sx  = t0.x+t1.x+t2.x+t3.x;
            float sx2 = t0.y+t1.y+t2.y+t3.y;
            float sy  = t0.z+t1.z+t2.z+t3.z;
            float sy2 = t0.w+t1.w+t2.w+t3.w;
            float mx = sx*(1.f/CC), my = sy*(1.f/CC);
            int p = b*LL + n0 + 2*tid;
            g_mu_x[p]   = mx; g_rs_x[p]   = rsqrtf(fmaf(-mx, mx, sx2*(1.f/CC)) + 1e-5f);
            g_mu_x[p+1] = my; g_rs_x[p+1] = rsqrtf(fmaf(-my, my, sy2*(1.f/CC)) + 1e-5f);
        }
    }
}

// ---------------------------------------------------------------------------
// Attention S via mma.sync + softmax -> packed fp16 A
// ---------------------------------------------------------------------------
#define QSTR 528
#define ATILE (32*QSTR)
#define ASTAGE (2*ATILE)
#define AS_SMEM (2*ASTAGE)

__global__ __launch_bounds__(256, 2)
void attn_s_kernel()
{
    extern __shared__ __align__(128) char smem[];
    const u32 sbase = smem_u32(smem);
    int bh = blockIdx.x, sp = blockIdx.y;
    int b = bh >> 3, h = bh & 7;
    int tid = threadIdx.x, lane = tid & 31, wid = tid >> 5;
    const u32* qp = g_q16  + ((size_t)b*CC   + h*HCC)*(LL/2) + sp*1024;
    const u32* kp = g_kv16 + ((size_t)b*2*CC + h*HCC)*(LL/2) + sp*1024;

    float acc[2][4][4];
#pragma unroll
    for (int i=0;i<2;i++)
#pragma unroll
        for (int j=0;j<4;j++)
#pragma unroll
            for (int r=0;r<4;r++) acc[i][j][r]=0.f;

#define ISSUEA(st, ch) do { \
        u32 so = sbase + (u32)((st)*ASTAGE); \
        _Pragma("unroll") \
        for (int ii = tid; ii < 1024; ii += 256) { \
            int row = ii >> 5, seg = ii & 31; \
            CP16(so + (u32)(row*QSTR + seg*16), \
                 qp + (size_t)row*(LL/2) + (ch)*128 + seg*4); \
            CP16(so + (u32)(ATILE + row*QSTR + seg*16), \
                 kp + (size_t)row*(LL/2) + (ch)*128 + seg*4); \
        } \
        CP_COMMIT(); \
    } while(0)

    ISSUEA(0, 0);
    u32 woff = (u32)(wid * 64);
#pragma unroll 1
    for (int ch = 0; ch < 8; ch++) {
        int cur = ch & 1;
        if (ch + 1 < 8) { ISSUEA(cur ^ 1, ch + 1); CP_WAIT(1); }
        else            { CP_WAIT(0); }
        __syncthreads();
        u32 qb = sbase + (u32)(cur*ASTAGE);
        u32 kb = qb + ATILE;
#pragma unroll
        for (int s = 0; s < 2; s++) {
            u32 koff = woff + (u32)(s*32);
            u32 af[2][4], bf[4][2];
            u32 aaddr = qb + (u32)((lane & 15)*QSTR) + ((lane & 16) ? 16u : 0u) + koff;
            LDSM_X4(af[0][0], af[0][1], af[0][2], af[0][3], aaddr);
            LDSM_X4(af[1][0], af[1][1], af[1][2], af[1][3], aaddr + (u32)(16*QSTR));
            u32 baddr = kb + (u32)(((lane & 7) + ((lane & 16) ? 8 : 0))*QSTR)
                      + ((lane & 8) ? 16u : 0u) + koff;
            LDSM_X4(bf[0][0], bf[0][1], bf[1][0], bf[1][1], baddr);
            LDSM_X4(bf[2][0], bf[2][1], bf[3][0], bf[3][1], baddr + (u32)(16*QSTR));
#pragma unroll
            for (int i = 0; i < 2; i++)
#pragma unroll
                for (int j = 0; j < 4; j++)
                    MMA_F16(acc[i][j], af[i], bf[j][0], bf[j][1]);
        }
        __syncthreads();
    }
#undef ISSUEA

    float* part = (float*)smem;
#pragma unroll
    for (int i = 0; i < 2; i++)
#pragma unroll
        for (int j = 0; j < 4; j++)
#pragma unroll
            for (int r = 0; r < 4; r++) {
                int row = i*16 + (lane >> 2) + ((r & 2) ? 8 : 0);
                int col = j*8 + (lane & 3)*2 + (r & 1);
                part[wid*1024 + row*32 + col] = acc[i][j][r];
            }
    __syncthreads();
    float* out = g_Sp + ((size_t)bh*NSP + sp)*1024;
#pragma unroll
    for (int e = tid; e < 1024; e += 256) {
        float s = 0.f;
#pragma unroll
        for (int w = 0; w < 8; w++) s += part[w*1024 + e];
        out[e] = s;
    }
}

__global__ void attn_softmax_kernel()
{
    int bh = blockIdx.x, t = threadIdx.x;
    const float* sp = g_Sp + (size_t)bh*NSP*1024 + t;
    float s = sp[0] + sp[1024];
    s *= 0.17677669529663687f;
    float mx = s;
#pragma unroll
    for (int o = 16; o > 0; o >>= 1) mx = fmaxf(mx, __shfl_xor_sync(0xffffffffu, mx, o));
    float e = expf(s - mx);
    float sum = e;
#pragma unroll
    for (int o = 16; o > 0; o >>= 1) sum += __shfl_xor_sync(0xffffffffu, sum, o);
    float a = e / sum;
    float ap = __shfl_xor_sync(0xffffffffu, a, 1);
    int c = t >> 5, d = t & 31;
    if (!(d & 1)) g_A16[(size_t)bh*512 + c*16 + (d >> 1)] = packf16(a, ap);
}

// ---------------------------------------------------------------------------
// Launcher
// ---------------------------------------------------------------------------
#define GS_128 (2*(128*A_STR + 64*(128*2+16)))   // 71680

extern "C" void kernel_launch(void* const* d_in, const int* in_sizes, int n_in,
                              void* d_out, int out_size)
{
    (void)in_sizes; (void)n_in; (void)out_size;
    const float* optical = (const float*)d_in[0];
    const float* sar     = (const float*)d_in[1];
    const float* gopt    = (const float*)d_in[2];
    const float* bopt    = (const float*)d_in[3];
    const float* gsar    = (const float*)d_in[4];
    const float* bsar    = (const float*)d_in[5];
    const float* Wq      = (const float*)d_in[6];
    const float* Wk      = (const float*)d_in[7];
    const float* Wv      = (const float*)d_in[8];
    const float* Wo      = (const float*)d_in[9];
    const float* gffn    = (const float*)d_in[10];
    const float* bffn    = (const float*)d_in[11];
    const float* W1      = (const float*)d_in[12];
    const float* b1      = (const float*)d_in[13];
    const float* W2      = (const float*)d_in[14];
    const float* b2      = (const float*)d_in[15];
    float* out = (float*)d_out;

    float *p_ws1,*p_wb1,*p_mu_x,*p_rs_x;
    u32 *p_A1,*p_A2,*p_x16,*p_hg;
    cudaGetSymbolAddress((void**)&p_ws1, g_ws1);     cudaGetSymbolAddress((void**)&p_wb1, g_wb1v);
    cudaGetSymbolAddress((void**)&p_mu_x, g_mu_x);   cudaGetSymbolAddress((void**)&p_rs_x, g_rs_x);
    cudaGetSymbolAddress((void**)&p_A1, g_A1);       cudaGetSymbolAddress((void**)&p_A2, g_A2);
    cudaGetSymbolAddress((void**)&p_x16, g_x16);     cudaGetSymbolAddress((void**)&p_hg, g_hg);

    cudaFuncSetAttribute((void*)gemm_qkv,                    cudaFuncAttributeMaxDynamicSharedMemorySize, GS_128);
    cudaFuncSetAttribute((void*)gemm_wo_av,                  cudaFuncAttributeMaxDynamicSharedMemorySize, WO_SMEM);
    cudaFuncSetAttribute((void*)gemm_mma<3,256,FH2,128,128>, cudaFuncAttributeMaxDynamicSharedMemorySize, GS_128);
    cudaFuncSetAttribute((void*)gemm_mma<2,512,256,128,128>, cudaFuncAttributeMaxDynamicSharedMemorySize, GS_128);
    cudaFuncSetAttribute((void*)attn_s_kernel,               cudaFuncAttributeMaxDynamicSharedMemorySize, AS_SMEM);

    // 1) combined weight prep + LN stats + fp16 conversion (one launch)
    prep_ln_kernel<<<1792, 512>>>(optical, sar, Wq, Wk, Wv, W1, Wo, W2,
                                  gopt, bopt, gsar, bsar, gffn, bffn, b1);

    // 2) fused Q + K/V projections -> fp16
    gemm_qkv<<<dim3(32, 6, BB), 256, GS_128>>>();

    // 3) channel attention: MMA partial S (2 L-splits), softmax -> fp16 A
    attn_s_kernel<<<dim3(BB*NHH, NSP), 256, AS_SMEM>>>();
    attn_softmax_kernel<<<BB*NHH, 1024>>>();

    // 4) Wo GEMM with inline A@V + residual(optical) + LN stats -> x16
    gemm_wo_av<<<dim3(64, 1, BB), 256, WO_SMEM>>>(optical);

    // 5) W1 (LN+b1 folded, row-paired) + fused SimpleGate -> hg (fp16)
    gemm_mma<3,256,FH2,128,128><<<dim3(32,8,BB),256,GS_128>>>(p_A1, p_x16, (void*)0, p_mu_x, p_rs_x, p_ws1, p_wb1, 0, 0);

    // 6) W2 + b2 + residual(x16) -> out fp32
    gemm_mma<2,512,256,128,128><<<dim3(32,2,BB),256,GS_128>>>(p_A2, p_hg, out, 0, 0, 0, 0, p_x16, b2);
}